// round 10
// baseline (speedup 1.0000x reference)
#include <cuda_runtime.h>
#include <cstdint>

// Problem constants (fixed by the reference)
#define C_CELLS        500000
#define NB             10
#define QF4            4                      // Q=16 -> 4 float4 per cell
#define F4_PER_CELL    (NB * QF4)             // 40 float4 = 640 B per cell
#define CELLS_PER_TILE 64
#define TILE_F4        (CELLS_PER_TILE * F4_PER_CELL)  // 2560
#define BLOCK          256
#define ITERS          (TILE_F4 / BLOCK)      // 10

__device__ __forceinline__ void cp_async16(uint32_t smem_addr, const void* gptr) {
    asm volatile("cp.async.cg.shared.global [%0], [%1], 16;\n"
                 :: "r"(smem_addr), "l"(gptr) : "memory");
}
__device__ __forceinline__ void cp_async_commit() {
    asm volatile("cp.async.commit_group;\n" ::: "memory");
}
__device__ __forceinline__ void cp_async_wait_all() {
    asm volatile("cp.async.wait_group 0;\n" ::: "memory");
}

__global__ __launch_bounds__(BLOCK)
void quad_fn_kernel(
    const float*  __restrict__ vertex_dofs,     // [V,1]
    const float2* __restrict__ edge_dofs,       // [E,2]
    const float*  __restrict__ face_dofs,       // [C,1]
    const float4* __restrict__ y,               // [C,NB,16] as float4 [C*40]
    const int*    __restrict__ faces,           // [C,3]
    const int*    __restrict__ faces_to_edges,  // [C,3]
    const int*    __restrict__ edge_orientation,// [C,3]
    float4*       __restrict__ out)             // [C,16] as float4 [C*4]
{
    // y tile, XOR-swizzled 16B columns within each 640B cell row (no padding,
    // conflict-free LDS.128 in compute phase): 40960 B
    __shared__ float4 y_s[TILE_F4];
    // per-cell weights, row padded to 11 floats (conflict-free scalar LDS)
    __shared__ float  w_s[CELLS_PER_TILE][11];
    // output staging, row padded to 20 floats
    __shared__ float  o_s[CELLS_PER_TILE][20];

    const int tile  = blockIdx.x;
    const int t     = threadIdx.x;
    const int cell0 = tile * CELLS_PER_TILE;
    const int cells_in_tile = min(CELLS_PER_TILE, C_CELLS - cell0);
    const int nf4 = cells_in_tile * F4_PER_CELL;

    const uint32_t ys_addr = (uint32_t)__cvta_generic_to_shared(y_s);
    const float4* ybase = y + (size_t)cell0 * F4_PER_CELL;

    // ---- Phase 1: async bulk-load y tile (L1-bypass, fully coalesced) ----
    #pragma unroll
    for (int i = 0; i < ITERS; ++i) {
        const int r = i * BLOCK + t;
        if (r < nf4) {
            const int c   = r / F4_PER_CELL;              // const-div -> mul/shift
            const int off = (r - c * F4_PER_CELL) * 16;   // bytes within cell row
            const uint32_t dst = ys_addr + c * 640 + (off ^ ((c & 7) << 4));
            cp_async16(dst, ybase + r);
        }
    }
    cp_async_commit();

    // ---- Phase 2: gather per-cell weights (once per cell, threads 0..63) ----
    if (t < CELLS_PER_TILE) {
        const int cg = cell0 + t;
        if (cg < C_CELLS) {
            const int b3 = cg * 3;
            w_s[t][0] = __ldg(&vertex_dofs[__ldg(&faces[b3 + 0])]);
            w_s[t][1] = __ldg(&vertex_dofs[__ldg(&faces[b3 + 1])]);
            w_s[t][2] = __ldg(&vertex_dofs[__ldg(&faces[b3 + 2])]);
            #pragma unroll
            for (int i = 0; i < 3; ++i) {
                const int    e  = __ldg(&faces_to_edges[b3 + i]);
                const int    o  = __ldg(&edge_orientation[b3 + i]);
                const float2 ed = __ldg(&edge_dofs[e]);
                // orientation==1: keep (x,y); orientation==0: flipped (y,x)
                w_s[t][3 + 2 * i]     = o ? ed.x : ed.y;
                w_s[t][3 + 2 * i + 1] = o ? ed.y : ed.x;
            }
            w_s[t][9] = __ldg(&face_dofs[cg]);
        }
    }

    cp_async_wait_all();
    __syncthreads();

    // ---- Phase 3: compute. thread -> (c = t%64, qg = t/64).
    //      Warp = 32 consecutive c, fixed qg: swizzle makes each 8-lane
    //      LDS.128 phase hit 8 distinct bank groups. ----
    {
        const int c  = t & 63;
        const int qg = t >> 6;
        float4 acc = make_float4(0.f, 0.f, 0.f, 0.f);
        if (c < cells_in_tile) {
            const char* yrow = reinterpret_cast<const char*>(y_s) + c * 640;
            const int   sw   = (c & 7) << 4;
            #pragma unroll
            for (int b = 0; b < NB; ++b) {
                const int offb = (b * 64 + qg * 16) ^ sw;
                const float4 v = *reinterpret_cast<const float4*>(yrow + offb);
                const float  w = w_s[c][b];
                acc.x = fmaf(w, v.x, acc.x);
                acc.y = fmaf(w, v.y, acc.y);
                acc.z = fmaf(w, v.z, acc.z);
                acc.w = fmaf(w, v.w, acc.w);
            }
        }
        *reinterpret_cast<float4*>(&o_s[c][qg * 4]) = acc;
    }
    __syncthreads();

    // ---- Phase 4: coalesced output (256 contiguous float4 stores) ----
    {
        const int c  = t >> 2;
        const int qg = t & 3;
        if (c < cells_in_tile) {
            const float4 v = *reinterpret_cast<const float4*>(&o_s[c][qg * 4]);
            __stcs(out + (size_t)cell0 * 4 + t, v);
        }
    }
}

extern "C" void kernel_launch(void* const* d_in, const int* in_sizes, int n_in,
                              void* d_out, int out_size)
{
    // metadata order: vertex_dofs, edge_dofs, face_dofs, y, faces,
    //                 faces_to_edges, edge_orientation
    const float*  vertex_dofs      = (const float*) d_in[0];
    const float2* edge_dofs        = (const float2*)d_in[1];
    const float*  face_dofs        = (const float*) d_in[2];
    const float4* y                = (const float4*)d_in[3];
    const int*    faces            = (const int*)   d_in[4];
    const int*    faces_to_edges   = (const int*)   d_in[5];
    const int*    edge_orientation = (const int*)   d_in[6];
    float4*       out              = (float4*)      d_out;

    const int grid = (C_CELLS + CELLS_PER_TILE - 1) / CELLS_PER_TILE;  // 7813

    quad_fn_kernel<<<grid, BLOCK>>>(vertex_dofs, edge_dofs, face_dofs, y,
                                    faces, faces_to_edges, edge_orientation, out);
}

// round 11
// speedup vs baseline: 1.0738x; 1.0738x over previous
#include <cuda_runtime.h>

// Problem constants (fixed by the reference)
#define C_CELLS 500000
#define NB 10
// Each thread handles 2 adjacent cells x one float4 of quadrature points.
// total threads = (C/2) * 4 = 1,000,000

__device__ __forceinline__ float4 ldcg4(const float4* p) { return __ldcg(p); }

__global__ __launch_bounds__(256)
void quad_fn_kernel(
    const float*  __restrict__ vertex_dofs,     // [V,1]
    const float2* __restrict__ edge_dofs,       // [E,2]
    const float*  __restrict__ face_dofs,       // [C,1]
    const float4* __restrict__ y,               // [C,NB,16] as float4 [C*40]
    const int*    __restrict__ faces,           // [C,3]
    const int*    __restrict__ faces_to_edges,  // [C,3]
    const int*    __restrict__ edge_orientation,// [C,3]
    float4*       __restrict__ out)             // [C,16] as float4 [C*4]
{
    const int gid  = blockIdx.x * blockDim.x + threadIdx.x;
    const int pair = gid >> 2;            // cell pair
    const int qg   = gid & 3;             // which float4 of the 16 q-points
    const int c0   = pair * 2;
    if (c0 >= C_CELLS) return;
    const int c1   = c0 + 1;              // C_CELLS is even -> always valid

    // ---- Gather local dofs for both cells (broadcast across the 4 lanes
    //      sharing each cell; index rows for c0/c1 share cache lines) ----
    float d0[NB], d1[NB];

    {
        const int b3 = c0 * 3;
        d0[0] = __ldg(&vertex_dofs[__ldg(&faces[b3 + 0])]);
        d0[1] = __ldg(&vertex_dofs[__ldg(&faces[b3 + 1])]);
        d0[2] = __ldg(&vertex_dofs[__ldg(&faces[b3 + 2])]);
        #pragma unroll
        for (int i = 0; i < 3; ++i) {
            const int    e  = __ldg(&faces_to_edges[b3 + i]);
            const int    o  = __ldg(&edge_orientation[b3 + i]);
            const float2 ed = __ldg(&edge_dofs[e]);
            d0[3 + 2 * i]     = o ? ed.x : ed.y;
            d0[3 + 2 * i + 1] = o ? ed.y : ed.x;
        }
        d0[9] = __ldg(&face_dofs[c0]);
    }
    {
        const int b3 = c1 * 3;
        d1[0] = __ldg(&vertex_dofs[__ldg(&faces[b3 + 0])]);
        d1[1] = __ldg(&vertex_dofs[__ldg(&faces[b3 + 1])]);
        d1[2] = __ldg(&vertex_dofs[__ldg(&faces[b3 + 2])]);
        #pragma unroll
        for (int i = 0; i < 3; ++i) {
            const int    e  = __ldg(&faces_to_edges[b3 + i]);
            const int    o  = __ldg(&edge_orientation[b3 + i]);
            const float2 ed = __ldg(&edge_dofs[e]);
            d1[3 + 2 * i]     = o ? ed.x : ed.y;
            d1[3 + 2 * i + 1] = o ? ed.y : ed.x;
        }
        d1[9] = __ldg(&face_dofs[c1]);
    }

    // ---- Two independent y streams (20 outstanding LDG.128 total).
    //      Per-warp geometry per instruction: 8 cells x 64B segments,
    //      same as the best (R1) layout. L1-bypass: y has zero reuse. ----
    const float4* yp0 = y + (size_t)c0 * (NB * 4) + qg;
    const float4* yp1 = y + (size_t)c1 * (NB * 4) + qg;

    float4 a0 = make_float4(0.f, 0.f, 0.f, 0.f);
    float4 a1 = make_float4(0.f, 0.f, 0.f, 0.f);

    #pragma unroll
    for (int b = 0; b < NB; ++b) {
        const float4 v0 = ldcg4(&yp0[b * 4]);
        const float4 v1 = ldcg4(&yp1[b * 4]);
        const float  w0 = d0[b];
        const float  w1 = d1[b];
        a0.x = fmaf(w0, v0.x, a0.x);
        a0.y = fmaf(w0, v0.y, a0.y);
        a0.z = fmaf(w0, v0.z, a0.z);
        a0.w = fmaf(w0, v0.w, a0.w);
        a1.x = fmaf(w1, v1.x, a1.x);
        a1.y = fmaf(w1, v1.y, a1.y);
        a1.z = fmaf(w1, v1.z, a1.z);
        a1.w = fmaf(w1, v1.w, a1.w);
    }

    __stcg(out + (size_t)c0 * 4 + qg, a0);
    __stcg(out + (size_t)c1 * 4 + qg, a1);
}

extern "C" void kernel_launch(void* const* d_in, const int* in_sizes, int n_in,
                              void* d_out, int out_size)
{
    // metadata order: vertex_dofs, edge_dofs, face_dofs, y, faces,
    //                 faces_to_edges, edge_orientation
    const float*  vertex_dofs      = (const float*) d_in[0];
    const float2* edge_dofs        = (const float2*)d_in[1];
    const float*  face_dofs        = (const float*) d_in[2];
    const float4* y                = (const float4*)d_in[3];
    const int*    faces            = (const int*)   d_in[4];
    const int*    faces_to_edges   = (const int*)   d_in[5];
    const int*    edge_orientation = (const int*)   d_in[6];
    float4*       out              = (float4*)      d_out;

    const int total_threads = (C_CELLS / 2) * 4;   // 1,000,000
    const int block = 256;
    const int grid  = (total_threads + block - 1) / block;

    quad_fn_kernel<<<grid, block>>>(vertex_dofs, edge_dofs, face_dofs, y,
                                    faces, faces_to_edges, edge_orientation, out);
}

// round 12
// speedup vs baseline: 1.2353x; 1.1504x over previous
#include <cuda_runtime.h>

// Problem constants (fixed by the reference)
#define C_CELLS 500000
#define NB 10
#define THREADS_PER_CELL 4   // each thread handles 4 quadrature points (float4)

__global__ __launch_bounds__(256)
void quad_fn_kernel(
    const float*  __restrict__ vertex_dofs,     // [V,1]
    const float2* __restrict__ edge_dofs,       // [E,2]
    const float*  __restrict__ face_dofs,       // [C,1]
    const float4* __restrict__ y,               // [C,NB,16] as float4 [C*40]
    const int*    __restrict__ faces,           // [C,3]
    const int*    __restrict__ faces_to_edges,  // [C,3]
    const int*    __restrict__ edge_orientation,// [C,3]
    float4*       __restrict__ out)             // [C,16] as float4 [C*4]
{
    const int gid = blockIdx.x * blockDim.x + threadIdx.x;
    const int c  = gid >> 2;          // cell
    const int qg = gid & 3;           // which float4 of the 16 q-points
    if (c >= C_CELLS) return;

    // ---- Gather local dofs (identical across the 4 lanes of this cell;
    //      warp coalesces these into broadcast transactions). These tables
    //      are small and reused -> default caching keeps them in L1/L2. ----
    float d[NB];

    const int base3 = c * 3;
    #pragma unroll
    for (int i = 0; i < 3; ++i) {
        d[i] = __ldg(&vertex_dofs[__ldg(&faces[base3 + i])]);
    }
    #pragma unroll
    for (int i = 0; i < 3; ++i) {
        const int    e  = __ldg(&faces_to_edges[base3 + i]);
        const float2 ed = __ldg(&edge_dofs[e]);
        const int    o  = __ldg(&edge_orientation[base3 + i]);
        // orientation==1: keep (e0,e1); orientation==0: flipped (e1,e0)
        d[3 + 2 * i]     = o ? ed.x : ed.y;
        d[3 + 2 * i + 1] = o ? ed.y : ed.x;
    }
    d[9] = __ldg(&face_dofs[c]);

    // ---- Weighted sum over basis functions on a float4 of q-points.
    //      y is a 320MB zero-reuse stream: bypass L1 allocation (.cg) so it
    //      doesn't evict the gather tables or burn L1 fill bandwidth. ----
    const float4* yp = y + (size_t)c * (NB * 4) + qg;

    float4 acc = make_float4(0.f, 0.f, 0.f, 0.f);
    #pragma unroll
    for (int b = 0; b < NB; ++b) {
        const float4 v = __ldcg(&yp[b * 4]);
        const float  w = d[b];
        acc.x = fmaf(w, v.x, acc.x);
        acc.y = fmaf(w, v.y, acc.y);
        acc.z = fmaf(w, v.z, acc.z);
        acc.w = fmaf(w, v.w, acc.w);
    }

    __stcg(out + (size_t)c * 4 + qg, acc);
}

extern "C" void kernel_launch(void* const* d_in, const int* in_sizes, int n_in,
                              void* d_out, int out_size)
{
    // metadata order: vertex_dofs, edge_dofs, face_dofs, y, faces,
    //                 faces_to_edges, edge_orientation
    const float*  vertex_dofs      = (const float*) d_in[0];
    const float2* edge_dofs        = (const float2*)d_in[1];
    const float*  face_dofs        = (const float*) d_in[2];
    const float4* y                = (const float4*)d_in[3];
    const int*    faces            = (const int*)   d_in[4];
    const int*    faces_to_edges   = (const int*)   d_in[5];
    const int*    edge_orientation = (const int*)   d_in[6];
    float4*       out              = (float4*)      d_out;

    const int total_threads = C_CELLS * THREADS_PER_CELL;  // 2,000,000
    const int block = 256;
    const int grid  = (total_threads + block - 1) / block;

    quad_fn_kernel<<<grid, block>>>(vertex_dofs, edge_dofs, face_dofs, y,
                                    faces, faces_to_edges, edge_orientation, out);
}